// round 16
// baseline (speedup 1.0000x reference)
#include <cuda_runtime.h>
#include <cuda_fp16.h>

#define T_TOK  4096
#define DMODEL 1024
#define DFF    4096
#define NEXP   8
#define NSLOT  (T_TOK * 2)

#define BM 128
#define BK 32                       // K elems per chunk
#define ROWB 80                     // padded row pitch bytes (64B data + 16B pad)
#define EPITCH 132                  // fp32 epilogue row pitch (words, MODE0)
#define SMEM_M0 67584               // MODE0: max(2 stages 40960, epilogue 67584)
#define SMEM_M1 30720               // MODE1: 2 stages x (10240 + 64*80)

// ---------------------------------------------------------------------------
// Scratch
// ---------------------------------------------------------------------------
__device__ int   g_cnt[NEXP];
__device__ int   g_list[NEXP][T_TOK];
__device__ float g_wt[NEXP][T_TOK];
__device__ __half g_x_h[(size_t)T_TOK * DMODEL];
__device__ __half g_w1_h[(size_t)NEXP * DFF * DMODEL];   // transposed [e][f][d]
__device__ __half g_w2_h[(size_t)NEXP * DMODEL * DFF];   // transposed [e][d][f]
__device__ __half g_h_h[(size_t)NSLOT * DFF];

// ---------------------------------------------------------------------------
// PTX helpers (sm_80-class PTX only; tcgen05 rejected on plain sm_103 target)
// ---------------------------------------------------------------------------
__device__ __forceinline__ unsigned smem_u32(const void* p) {
    unsigned a;
    asm("{ .reg .u64 t; cvta.to.shared.u64 t, %1; cvt.u32.u64 %0, t; }"
        : "=r"(a) : "l"(p));
    return a;
}
__device__ __forceinline__ void cp16(unsigned d, const void* s) {
    asm volatile("cp.async.cg.shared.global [%0], [%1], 16;"
                 :: "r"(d), "l"(s) : "memory");
}
__device__ __forceinline__ void cp_commit() {
    asm volatile("cp.async.commit_group;" ::: "memory");
}
template<int N> __device__ __forceinline__ void cp_wait() {
    asm volatile("cp.async.wait_group %0;" :: "n"(N) : "memory");
}
__device__ __forceinline__ uint4 ldsm4(unsigned a) {
    uint4 r;
    asm volatile("ldmatrix.sync.aligned.m8n8.x4.shared.b16 {%0,%1,%2,%3}, [%4];"
                 : "=r"(r.x), "=r"(r.y), "=r"(r.z), "=r"(r.w) : "r"(a));
    return r;
}
__device__ __forceinline__ void mma16816(float* c, const uint4& a,
                                         unsigned b0, unsigned b1) {
    asm volatile(
        "mma.sync.aligned.m16n8k16.row.col.f32.f16.f16.f32 "
        "{%0,%1,%2,%3},{%4,%5,%6,%7},{%8,%9},{%0,%1,%2,%3};"
        : "+f"(c[0]), "+f"(c[1]), "+f"(c[2]), "+f"(c[3])
        : "r"(a.x), "r"(a.y), "r"(a.z), "r"(a.w), "r"(b0), "r"(b1));
}
__device__ __forceinline__ unsigned short h16(float v) {
    return __half_as_ushort(__float2half_rn(v));
}
__device__ __forceinline__ unsigned pk2(float a, float b) {
    return (unsigned)h16(a) | ((unsigned)h16(b) << 16);
}

// ---------------------------------------------------------------------------
// Small kernels
// ---------------------------------------------------------------------------
__global__ void zero_cnt_kernel() {
    if (threadIdx.x < NEXP) g_cnt[threadIdx.x] = 0;
}

__global__ void zero_out_kernel(float* __restrict__ out) {
    size_t i = ((size_t)blockIdx.x * blockDim.x + threadIdx.x) * 4;
    *(float4*)(out + i) = make_float4(0.f, 0.f, 0.f, 0.f);
}

// gating + fp16 convert of x fused: one pass over x.
__global__ void gate_kernel(const float* __restrict__ x,
                            const float* __restrict__ Wg) {
    int gwarp = (blockIdx.x * blockDim.x + threadIdx.x) >> 5;
    int lane  = threadIdx.x & 31;
    if (gwarp >= T_TOK) return;
    int t = gwarp;
    const float* xr = x + (size_t)t * DMODEL;
    __half* xo = g_x_h + (size_t)t * DMODEL;
    float acc[NEXP];
#pragma unroll
    for (int e = 0; e < NEXP; e++) acc[e] = 0.f;
    for (int d = lane; d < DMODEL; d += 32) {
        float xv = xr[d];
        xo[d] = __ushort_as_half(h16(xv));
        const float* wr = Wg + d * NEXP;
#pragma unroll
        for (int e = 0; e < NEXP; e++) acc[e] += xv * wr[e];
    }
#pragma unroll
    for (int e = 0; e < NEXP; e++)
#pragma unroll
        for (int off = 16; off; off >>= 1)
            acc[e] += __shfl_xor_sync(0xFFFFFFFFu, acc[e], off);
    if (lane == 0) {
        int i0 = 0; float l0 = acc[0];
#pragma unroll
        for (int e = 1; e < NEXP; e++) if (acc[e] > l0) { l0 = acc[e]; i0 = e; }
        int i1 = -1; float l1 = -3.0e38f;
#pragma unroll
        for (int e = 0; e < NEXP; e++)
            if (e != i0 && acc[e] > l1) { l1 = acc[e]; i1 = e; }
        float w0 = 1.0f / (1.0f + expf(l1 - l0));
        float w1 = 1.0f - w0;
        int p0 = atomicAdd(&g_cnt[i0], 1);
        g_list[i0][p0] = t * 2 + 0; g_wt[i0][p0] = w0;
        int p1 = atomicAdd(&g_cnt[i1], 1);
        g_list[i1][p1] = t * 2 + 1; g_wt[i1][p1] = w1;
    }
}

// transpose + fp16 convert: in [R][C] fp32 per expert -> out [C][R] fp16
template<int WSEL>
__global__ void transp_conv_kernel(const float* __restrict__ in) {
    const int R = (WSEL == 0) ? DMODEL : DFF;
    const int C = (WSEL == 0) ? DFF : DMODEL;
    __half* oh = (WSEL == 0) ? g_w1_h : g_w2_h;
    __shared__ float t[64][33];
    size_t eb = (size_t)blockIdx.z * (size_t)R * C;
    int c0 = blockIdx.x * 32, r0 = blockIdx.y * 64;
    int tx = threadIdx.x, ty = threadIdx.y;
    for (int i = ty; i < 64; i += 8)
        t[i][tx] = in[eb + (size_t)(r0 + i) * C + c0 + tx];
    __syncthreads();
    int tid  = ty * 32 + tx;
    int orow = tid >> 3;           // 0..31 (C index)
    int rg   = (tid & 7) * 8;      // 0..56 (R group)
    uint4 v;
    v.x = pk2(t[rg + 0][orow], t[rg + 1][orow]);
    v.y = pk2(t[rg + 2][orow], t[rg + 3][orow]);
    v.z = pk2(t[rg + 4][orow], t[rg + 5][orow]);
    v.w = pk2(t[rg + 6][orow], t[rg + 7][orow]);
    *(uint4*)(oh + eb + (size_t)(c0 + orow) * R + r0 + rg) = v;
}

// ---------------------------------------------------------------------------
// Grouped GEMM via mma.sync fp16 (fp32 acc), 2-stage cp.async.
// MODE 0: BNT=128, 2 CTA/SM. A=g_x_h, B=g_w1 -> h=relu(acc+b1) fp16 (smem ep.)
// MODE 1: BNT=64,  3 CTA/SM. A=g_h_h, B=g_w2 -> atomicAdd out += w*(acc+b2)
//         (register-direct; exactly 2 commutative adds per element -> bitwise
//          deterministic)
// ---------------------------------------------------------------------------
template<int KTOT, int NTOT, int MODE, int BNT, int MINB>
__global__ void __launch_bounds__(256, MINB)
moe_gemm_kernel(const float* __restrict__ bias, float* __restrict__ outp) {
    extern __shared__ __align__(128) char smem[];
    constexpr int OFFB        = 128 * ROWB;          // A matrix bytes
    constexpr int STAGE_BYTES = OFFB + BNT * ROWB;   // A + B per stage
    constexpr int NP          = BNT / 32;            // B ldsm tiles per warp
    const int e   = blockIdx.z;
    const int cnt = g_cnt[e];
    const int mB  = blockIdx.y * BM;
    if (mB >= cnt) return;
    const int nB  = blockIdx.x * BNT;
    const int tid = threadIdx.x;
    const int lane = tid & 31;
    const int wid  = tid >> 5;
    const int warp_m = wid & 3;     // 4 warps along M (32 rows each)
    const int warp_n = wid >> 2;    // 2 warps along N (BNT/2 cols each)
    const int NCH = KTOT / BK;

    const __half* Ah = (MODE == 0) ? g_x_h : g_h_h;
    const __half* Bh = (MODE == 0) ? g_w1_h : g_w2_h;

    const unsigned sbase = smem_u32(smem);

    // A copy lanes: thread t loads row (t>>1), 32B seg (t&1)
    const char *pA;
    unsigned adst;
    {
        int arow = tid >> 1, aseg = (tid & 1) * 32;
        int m = mB + arow;
        int ar = 0;
        if (m < cnt) { int s = g_list[e][m]; ar = (MODE == 0) ? (s >> 1) : s; }
        pA = (const char*)(Ah + (size_t)ar * KTOT) + aseg;
        adst = arow * ROWB + aseg;
    }
    // B copy lanes
    const char *pB;
    unsigned bdst;
    {
        int brow, bseg;
        if (BNT == 128) { brow = tid >> 1; bseg = (tid & 1) * 32; }
        else            { brow = tid >> 2; bseg = (tid & 3) * 16; }
        size_t bo = (size_t)e * NTOT * KTOT + (size_t)(nB + brow) * KTOT;
        pB = (const char*)(Bh + bo) + bseg;
        bdst = brow * ROWB + bseg;
    }

#define LOADC(s, c) do { \
        unsigned st_ = sbase + (s) * STAGE_BYTES; \
        size_t ko_ = (size_t)(c) * (BK * 2); \
        cp16(st_ + adst,      pA + ko_); \
        cp16(st_ + adst + 16, pA + ko_ + 16); \
        if (BNT == 128) { \
            cp16(st_ + OFFB + bdst,      pB + ko_); \
            cp16(st_ + OFFB + bdst + 16, pB + ko_ + 16); \
        } else { \
            cp16(st_ + OFFB + bdst,      pB + ko_); \
        } \
    } while (0)

    unsigned aoff[2], boff[NP];
#pragma unroll
    for (int mt = 0; mt < 2; mt++)
        aoff[mt] = (unsigned)(warp_m * 32 + mt * 16 + (lane & 15)) * ROWB
                 + (unsigned)((lane >> 4) * 8) * 2;
#pragma unroll
    for (int p = 0; p < NP; p++)
        boff[p] = (unsigned)(warp_n * (BNT / 2) + p * 16 + ((lane >> 4) << 3) + (lane & 7)) * ROWB
                + (unsigned)(((lane >> 3) & 1) * 8) * 2;

    float acc[2][2 * NP][4];
#pragma unroll
    for (int i = 0; i < 2; i++)
#pragma unroll
        for (int j = 0; j < 2 * NP; j++)
#pragma unroll
            for (int q = 0; q < 4; q++) acc[i][j][q] = 0.f;

    LOADC(0, 0);
    cp_commit();

    for (int c = 0; c < NCH; c++) {
        if (c + 1 < NCH) {
            LOADC((c + 1) & 1, c + 1);
            cp_commit();
            cp_wait<1>();
        } else {
            cp_wait<0>();
        }
        __syncthreads();

        const unsigned st = sbase + (c & 1) * STAGE_BYTES;
#pragma unroll
        for (int ks = 0; ks < 2; ks++) {
            const unsigned ko = ks * 32;
            uint4 ah[2];
#pragma unroll
            for (int mt = 0; mt < 2; mt++)
                ah[mt] = ldsm4(st + aoff[mt] + ko);
            uint4 bh[NP];
#pragma unroll
            for (int p = 0; p < NP; p++)
                bh[p] = ldsm4(st + OFFB + boff[p] + ko);
#pragma unroll
            for (int mt = 0; mt < 2; mt++)
#pragma unroll
                for (int p = 0; p < NP; p++) {
                    mma16816(acc[mt][2 * p],     ah[mt], bh[p].x, bh[p].y);
                    mma16816(acc[mt][2 * p + 1], ah[mt], bh[p].z, bh[p].w);
                }
        }
        __syncthreads();
    }

    if (MODE == 0) {
        // ---------------- epilogue: acc -> smem fp32 -> g_h_h ----------------
        float* ep = (float*)smem;
        {
            int g = lane >> 2, q4 = lane & 3;
#pragma unroll
            for (int mt = 0; mt < 2; mt++) {
                int r0 = warp_m * 32 + mt * 16 + g;
#pragma unroll
                for (int nt = 0; nt < 2 * NP; nt++) {
                    int cc = warp_n * (BNT / 2) + nt * 8 + q4 * 2;
                    *(float2*)&ep[(size_t)r0 * EPITCH + cc] =
                        make_float2(acc[mt][nt][0], acc[mt][nt][1]);
                    *(float2*)&ep[(size_t)(r0 + 8) * EPITCH + cc] =
                        make_float2(acc[mt][nt][2], acc[mt][nt][3]);
                }
            }
        }
        __syncthreads();
        {
            int r = tid >> 1;
            int m = mB + r;
            if (m < cnt) {
                int slot = g_list[e][m];
                int c0 = (tid & 1) * 64;
                const float* row = ep + (size_t)r * EPITCH + c0;
                const float* bp = bias + (size_t)e * NTOT + nB + c0;
                __half* dh = g_h_h + (size_t)slot * NTOT + nB + c0;
#pragma unroll
                for (int g2 = 0; g2 < 8; g2++) {
                    ushort4 hv;
#pragma unroll
                    for (int j = 0; j < 8; j++) {
                        float v = fmaxf(row[g2 * 8 + j] + bp[g2 * 8 + j], 0.f);
                        ((unsigned short*)&hv)[j & 3] = h16(v);
                        if ((j & 3) == 3)
                            *(ushort4*)(dh + g2 * 8 + j - 3) = hv;
                    }
                }
            }
        }
    } else {
        // ------------- epilogue: register-direct atomic combine -------------
        int g = lane >> 2, q4 = lane & 3;
        const float* bp = bias + (size_t)e * NTOT + nB;
#pragma unroll
        for (int mt = 0; mt < 2; mt++) {
#pragma unroll
            for (int half = 0; half < 2; half++) {
                int m = mB + warp_m * 32 + mt * 16 + half * 8 + g;
                if (m < cnt) {
                    int slot = g_list[e][m];
                    float w  = g_wt[e][m];
                    float* orow = outp + (size_t)(slot >> 1) * NTOT + nB;
#pragma unroll
                    for (int nt = 0; nt < 2 * NP; nt++) {
                        int cc = warp_n * (BNT / 2) + nt * 8 + q4 * 2;
                        atomicAdd(orow + cc,
                                  w * (acc[mt][nt][2 * half + 0] + bp[cc]));
                        atomicAdd(orow + cc + 1,
                                  w * (acc[mt][nt][2 * half + 1] + bp[cc + 1]));
                    }
                }
            }
        }
    }
}

// ---------------------------------------------------------------------------
// Launch — both weight transposes forked (R12/R13-proven overlap).
// ---------------------------------------------------------------------------
extern "C" void kernel_launch(void* const* d_in, const int* in_sizes, int n_in,
                              void* d_out, int out_size) {
    const float* x  = (const float*)d_in[0];
    const float* Wg = (const float*)d_in[1];
    const float* W1 = (const float*)d_in[2];
    const float* b1 = (const float*)d_in[3];
    const float* W2 = (const float*)d_in[4];
    const float* b2 = (const float*)d_in[5];
    float* out = (float*)d_out;

    static cudaStream_t s2 = nullptr;
    static cudaEvent_t ev_fork = nullptr, ev_w1 = nullptr, ev_w2 = nullptr;
    if (s2 == nullptr) {
        cudaStreamCreateWithFlags(&s2, cudaStreamNonBlocking);
        cudaEventCreateWithFlags(&ev_fork, cudaEventDisableTiming);
        cudaEventCreateWithFlags(&ev_w1, cudaEventDisableTiming);
        cudaEventCreateWithFlags(&ev_w2, cudaEventDisableTiming);
        cudaFuncSetAttribute(moe_gemm_kernel<DMODEL, DFF, 0, 128, 1>,
                             cudaFuncAttributeMaxDynamicSharedMemorySize, SMEM_M0);
        cudaFuncSetAttribute(moe_gemm_kernel<DFF, DMODEL, 1, 64, 3>,
                             cudaFuncAttributeMaxDynamicSharedMemorySize, SMEM_M1);
    }

    dim3 tb(32, 8);

    // fork both weight transposes immediately
    cudaEventRecord(ev_fork, 0);
    cudaStreamWaitEvent(s2, ev_fork, 0);
    transp_conv_kernel<0><<<dim3(DFF / 32, DMODEL / 64, NEXP), tb, 0, s2>>>(W1);
    cudaEventRecord(ev_w1, s2);
    transp_conv_kernel<1><<<dim3(DMODEL / 32, DFF / 64, NEXP), tb, 0, s2>>>(W2);
    cudaEventRecord(ev_w2, s2);

    // main stream: zero out, gating (fused x convert)
    zero_cnt_kernel<<<1, 32>>>();
    zero_out_kernel<<<(T_TOK * DMODEL) / 4 / 256, 256>>>(out);
    gate_kernel<<<T_TOK / 8, 256>>>(x, Wg);

    cudaStreamWaitEvent(0, ev_w1, 0);
    moe_gemm_kernel<DMODEL, DFF, 0, 128, 1>
        <<<dim3(DFF / 128, T_TOK / BM, NEXP), 256, SMEM_M0>>>(b1, out);

    cudaStreamWaitEvent(0, ev_w2, 0);
    moe_gemm_kernel<DFF, DMODEL, 1, 64, 3>
        <<<dim3(DMODEL / 64, T_TOK / BM, NEXP), 256, SMEM_M1>>>(b2, out);
}

// round 17
// speedup vs baseline: 1.1064x; 1.1064x over previous
#include <cuda_runtime.h>
#include <cuda_fp16.h>

#define T_TOK  4096
#define DMODEL 1024
#define DFF    4096
#define NEXP   8
#define NSLOT  (T_TOK * 2)

#define BM 128
#define BN 128
#define BK 32                       // K elems per chunk
#define ROWB 80                     // padded row pitch bytes (64B data + 16B pad)
#define MATB (128 * ROWB)           // 10240 bytes per matrix
#define OFF_A 0
#define OFF_B MATB
#define STAGE_BYTES (2 * MATB)      // 20480
#define NSTAGE 3
#define SMEM_TOTAL 67584            // max(3 stages 61440, MODE0 epilogue 67584)
#define EPITCH 132                  // fp32 epilogue row pitch (words)

// ---------------------------------------------------------------------------
// Scratch
// ---------------------------------------------------------------------------
__device__ int   g_cnt[NEXP];
__device__ int   g_list[NEXP][T_TOK];
__device__ float g_wt[NEXP][T_TOK];
__device__ __half g_x_h[(size_t)T_TOK * DMODEL];
__device__ __half g_w1_h[(size_t)NEXP * DFF * DMODEL];   // transposed [e][f][d]
__device__ __half g_w2_h[(size_t)NEXP * DMODEL * DFF];   // transposed [e][d][f]
__device__ __half g_h_h[(size_t)NSLOT * DFF];

// ---------------------------------------------------------------------------
// PTX helpers (sm_80-class PTX only; tcgen05 rejected on plain sm_103 target)
// ---------------------------------------------------------------------------
__device__ __forceinline__ unsigned smem_u32(const void* p) {
    unsigned a;
    asm("{ .reg .u64 t; cvta.to.shared.u64 t, %1; cvt.u32.u64 %0, t; }"
        : "=r"(a) : "l"(p));
    return a;
}
__device__ __forceinline__ void cp16(unsigned d, const void* s) {
    asm volatile("cp.async.cg.shared.global [%0], [%1], 16;"
                 :: "r"(d), "l"(s) : "memory");
}
__device__ __forceinline__ void cp_commit() {
    asm volatile("cp.async.commit_group;" ::: "memory");
}
template<int N> __device__ __forceinline__ void cp_wait() {
    asm volatile("cp.async.wait_group %0;" :: "n"(N) : "memory");
}
__device__ __forceinline__ uint4 ldsm4(unsigned a) {
    uint4 r;
    asm volatile("ldmatrix.sync.aligned.m8n8.x4.shared.b16 {%0,%1,%2,%3}, [%4];"
                 : "=r"(r.x), "=r"(r.y), "=r"(r.z), "=r"(r.w) : "r"(a));
    return r;
}
__device__ __forceinline__ void mma16816(float* c, const uint4& a,
                                         unsigned b0, unsigned b1) {
    asm volatile(
        "mma.sync.aligned.m16n8k16.row.col.f32.f16.f16.f32 "
        "{%0,%1,%2,%3},{%4,%5,%6,%7},{%8,%9},{%0,%1,%2,%3};"
        : "+f"(c[0]), "+f"(c[1]), "+f"(c[2]), "+f"(c[3])
        : "r"(a.x), "r"(a.y), "r"(a.z), "r"(a.w), "r"(b0), "r"(b1));
}
__device__ __forceinline__ unsigned short h16(float v) {
    return __half_as_ushort(__float2half_rn(v));
}
__device__ __forceinline__ unsigned pk2(float a, float b) {
    return (unsigned)h16(a) | ((unsigned)h16(b) << 16);
}

// ---------------------------------------------------------------------------
// Small kernels
// ---------------------------------------------------------------------------
__global__ void zero_cnt_kernel() {
    if (threadIdx.x < NEXP) g_cnt[threadIdx.x] = 0;
}

__global__ void zero_out_kernel(float* __restrict__ out) {
    size_t i = ((size_t)blockIdx.x * blockDim.x + threadIdx.x) * 4;
    *(float4*)(out + i) = make_float4(0.f, 0.f, 0.f, 0.f);
}

// gating + fp16 convert of x fused: one pass over x.
__global__ void gate_kernel(const float* __restrict__ x,
                            const float* __restrict__ Wg) {
    int gwarp = (blockIdx.x * blockDim.x + threadIdx.x) >> 5;
    int lane  = threadIdx.x & 31;
    if (gwarp >= T_TOK) return;
    int t = gwarp;
    const float* xr = x + (size_t)t * DMODEL;
    __half* xo = g_x_h + (size_t)t * DMODEL;
    float acc[NEXP];
#pragma unroll
    for (int e = 0; e < NEXP; e++) acc[e] = 0.f;
    for (int d = lane; d < DMODEL; d += 32) {
        float xv = xr[d];
        xo[d] = __ushort_as_half(h16(xv));
        const float* wr = Wg + d * NEXP;
#pragma unroll
        for (int e = 0; e < NEXP; e++) acc[e] += xv * wr[e];
    }
#pragma unroll
    for (int e = 0; e < NEXP; e++)
#pragma unroll
        for (int off = 16; off; off >>= 1)
            acc[e] += __shfl_xor_sync(0xFFFFFFFFu, acc[e], off);
    if (lane == 0) {
        int i0 = 0; float l0 = acc[0];
#pragma unroll
        for (int e = 1; e < NEXP; e++) if (acc[e] > l0) { l0 = acc[e]; i0 = e; }
        int i1 = -1; float l1 = -3.0e38f;
#pragma unroll
        for (int e = 0; e < NEXP; e++)
            if (e != i0 && acc[e] > l1) { l1 = acc[e]; i1 = e; }
        float w0 = 1.0f / (1.0f + expf(l1 - l0));
        float w1 = 1.0f - w0;
        int p0 = atomicAdd(&g_cnt[i0], 1);
        g_list[i0][p0] = t * 2 + 0; g_wt[i0][p0] = w0;
        int p1 = atomicAdd(&g_cnt[i1], 1);
        g_list[i1][p1] = t * 2 + 1; g_wt[i1][p1] = w1;
    }
}

// transpose + fp16 convert: in [R][C] fp32 per expert -> out [C][R] fp16
template<int WSEL>
__global__ void transp_conv_kernel(const float* __restrict__ in) {
    const int R = (WSEL == 0) ? DMODEL : DFF;
    const int C = (WSEL == 0) ? DFF : DMODEL;
    __half* oh = (WSEL == 0) ? g_w1_h : g_w2_h;
    __shared__ float t[64][33];
    size_t eb = (size_t)blockIdx.z * (size_t)R * C;
    int c0 = blockIdx.x * 32, r0 = blockIdx.y * 64;
    int tx = threadIdx.x, ty = threadIdx.y;
    for (int i = ty; i < 64; i += 8)
        t[i][tx] = in[eb + (size_t)(r0 + i) * C + c0 + tx];
    __syncthreads();
    int tid  = ty * 32 + tx;
    int orow = tid >> 3;           // 0..31 (C index)
    int rg   = (tid & 7) * 8;      // 0..56 (R group)
    uint4 v;
    v.x = pk2(t[rg + 0][orow], t[rg + 1][orow]);
    v.y = pk2(t[rg + 2][orow], t[rg + 3][orow]);
    v.z = pk2(t[rg + 4][orow], t[rg + 5][orow]);
    v.w = pk2(t[rg + 6][orow], t[rg + 7][orow]);
    *(uint4*)(oh + eb + (size_t)(c0 + orow) * R + r0 + rg) = v;
}

// ---------------------------------------------------------------------------
// Grouped GEMM via mma.sync fp16 (fp32 acc), 3-stage cp.async ring with
// prefetch distance 1 and a SINGLE barrier per chunk (trailing barrier
// eliminated: the write into stage c%3 at iter c+2 happens after the iter-c+1
// barrier, which all threads pass only after computing stage c).
// MODE 0: A=g_x_h, B=g_w1 -> h = relu(acc + b1) stored fp16 (smem transpose)
// MODE 1: A=g_h_h, B=g_w2 -> atomicAdd out[token] += w * (acc + b2)
//         (register-direct; exactly 2 commutative adds per element)
// ---------------------------------------------------------------------------
template<int KTOT, int NTOT, int MODE>
__global__ void __launch_bounds__(256, 1)
moe_gemm_kernel(const float* __restrict__ bias, float* __restrict__ outp) {
    extern __shared__ __align__(128) char smem[];
    const int e   = blockIdx.z;
    const int cnt = g_cnt[e];
    const int mB  = blockIdx.y * BM;
    if (mB >= cnt) return;
    const int nB  = blockIdx.x * BN;
    const int tid = threadIdx.x;
    const int lane = tid & 31;
    const int wid  = tid >> 5;
    const int warp_m = wid & 3;     // 4 warps along M (32 rows each)
    const int warp_n = wid >> 2;    // 2 warps along N (64 cols each)
    const int NCH = KTOT / BK;

    const __half* Ah = (MODE == 0) ? g_x_h : g_h_h;
    const __half* Bh = (MODE == 0) ? g_w1_h : g_w2_h;

    const unsigned sbase = smem_u32(smem);

    const int crow = tid >> 1;
    const int cseg = (tid & 1) * 32;
    const char *pA, *pB;
    {
        int m = mB + crow;
        int ar = 0;
        if (m < cnt) { int s = g_list[e][m]; ar = (MODE == 0) ? (s >> 1) : s; }
        pA = (const char*)(Ah + (size_t)ar * KTOT) + cseg;
        size_t bo = (size_t)e * NTOT * KTOT + (size_t)(nB + crow) * KTOT;
        pB = (const char*)(Bh + bo) + cseg;
    }
    const unsigned cdst = crow * ROWB + cseg;

#define LOADC(s, c) do { \
        unsigned st_ = sbase + (s) * STAGE_BYTES + cdst; \
        size_t ko_ = (size_t)(c) * (BK * 2); \
        cp16(st_ + OFF_A,      pA + ko_); \
        cp16(st_ + OFF_A + 16, pA + ko_ + 16); \
        cp16(st_ + OFF_B,      pB + ko_); \
        cp16(st_ + OFF_B + 16, pB + ko_ + 16); \
    } while (0)

    unsigned aoff[2], boff[4];
#pragma unroll
    for (int mt = 0; mt < 2; mt++)
        aoff[mt] = (unsigned)(warp_m * 32 + mt * 16 + (lane & 15)) * ROWB
                 + (unsigned)((lane >> 4) * 8) * 2;
#pragma unroll
    for (int p = 0; p < 4; p++)
        boff[p] = (unsigned)(warp_n * 64 + p * 16 + ((lane >> 4) << 3) + (lane & 7)) * ROWB
                + (unsigned)(((lane >> 3) & 1) * 8) * 2;

    float acc[2][8][4];
#pragma unroll
    for (int i = 0; i < 2; i++)
#pragma unroll
        for (int j = 0; j < 8; j++)
#pragma unroll
            for (int q = 0; q < 4; q++) acc[i][j][q] = 0.f;

    LOADC(0, 0);
    cp_commit();

    int s_cur = 0, s_nxt = 1;
    for (int c = 0; c < NCH; c++) {
        if (c + 1 < NCH) {
            LOADC(s_nxt, c + 1);
            cp_commit();
            cp_wait<1>();
        } else {
            cp_wait<0>();
        }
        __syncthreads();   // single barrier per chunk (3-stage ring)

        const unsigned st = sbase + s_cur * STAGE_BYTES;
#pragma unroll
        for (int ks = 0; ks < 2; ks++) {
            const unsigned ko = ks * 32;
            uint4 ah[2];
#pragma unroll
            for (int mt = 0; mt < 2; mt++)
                ah[mt] = ldsm4(st + OFF_A + aoff[mt] + ko);
            uint4 bh[4];
#pragma unroll
            for (int p = 0; p < 4; p++)
                bh[p] = ldsm4(st + OFF_B + boff[p] + ko);
#pragma unroll
            for (int mt = 0; mt < 2; mt++)
#pragma unroll
                for (int p = 0; p < 4; p++) {
                    mma16816(acc[mt][2 * p],     ah[mt], bh[p].x, bh[p].y);
                    mma16816(acc[mt][2 * p + 1], ah[mt], bh[p].z, bh[p].w);
                }
        }
        s_cur = s_nxt;
        s_nxt = (s_nxt == NSTAGE - 1) ? 0 : s_nxt + 1;
    }
    __syncthreads();   // protect epilogue smem reuse (MODE 0)

    if (MODE == 0) {
        // ---------------- epilogue: acc -> smem fp32 -> g_h_h ----------------
        float* ep = (float*)smem;
        {
            int g = lane >> 2, q4 = lane & 3;
#pragma unroll
            for (int mt = 0; mt < 2; mt++) {
                int r0 = warp_m * 32 + mt * 16 + g;
#pragma unroll
                for (int nt = 0; nt < 8; nt++) {
                    int cc = warp_n * 64 + nt * 8 + q4 * 2;
                    *(float2*)&ep[(size_t)r0 * EPITCH + cc] =
                        make_float2(acc[mt][nt][0], acc[mt][nt][1]);
                    *(float2*)&ep[(size_t)(r0 + 8) * EPITCH + cc] =
                        make_float2(acc[mt][nt][2], acc[mt][nt][3]);
                }
            }
        }
        __syncthreads();
        {
            int r = tid >> 1;
            int m = mB + r;
            if (m < cnt) {
                int slot = g_list[e][m];
                int c0 = (tid & 1) * 64;
                const float* row = ep + (size_t)r * EPITCH + c0;
                const float* bp = bias + (size_t)e * NTOT + nB + c0;
                __half* dh = g_h_h + (size_t)slot * NTOT + nB + c0;
#pragma unroll
                for (int g2 = 0; g2 < 8; g2++) {
                    ushort4 hv;
#pragma unroll
                    for (int j = 0; j < 8; j++) {
                        float v = fmaxf(row[g2 * 8 + j] + bp[g2 * 8 + j], 0.f);
                        ((unsigned short*)&hv)[j & 3] = h16(v);
                        if ((j & 3) == 3)
                            *(ushort4*)(dh + g2 * 8 + j - 3) = hv;
                    }
                }
            }
        }
    } else {
        // ------------- epilogue: register-direct atomic combine -------------
        int g = lane >> 2, q4 = lane & 3;
        const float* bp = bias + (size_t)e * NTOT + nB;
#pragma unroll
        for (int mt = 0; mt < 2; mt++) {
#pragma unroll
            for (int half = 0; half < 2; half++) {
                int m = mB + warp_m * 32 + mt * 16 + half * 8 + g;
                if (m < cnt) {
                    int slot = g_list[e][m];
                    float w  = g_wt[e][m];
                    float* orow = outp + (size_t)(slot >> 1) * NTOT + nB;
#pragma unroll
                    for (int nt = 0; nt < 8; nt++) {
                        int cc = warp_n * 64 + nt * 8 + q4 * 2;
                        atomicAdd(orow + cc,
                                  w * (acc[mt][nt][2 * half + 0] + bp[cc]));
                        atomicAdd(orow + cc + 1,
                                  w * (acc[mt][nt][2 * half + 1] + bp[cc + 1]));
                    }
                }
            }
        }
    }
}

// ---------------------------------------------------------------------------
// Launch — both weight transposes forked (R12/R13-proven overlap).
// ---------------------------------------------------------------------------
extern "C" void kernel_launch(void* const* d_in, const int* in_sizes, int n_in,
                              void* d_out, int out_size) {
    const float* x  = (const float*)d_in[0];
    const float* Wg = (const float*)d_in[1];
    const float* W1 = (const float*)d_in[2];
    const float* b1 = (const float*)d_in[3];
    const float* W2 = (const float*)d_in[4];
    const float* b2 = (const float*)d_in[5];
    float* out = (float*)d_out;

    static cudaStream_t s2 = nullptr;
    static cudaEvent_t ev_fork = nullptr, ev_w1 = nullptr, ev_w2 = nullptr;
    if (s2 == nullptr) {
        cudaStreamCreateWithFlags(&s2, cudaStreamNonBlocking);
        cudaEventCreateWithFlags(&ev_fork, cudaEventDisableTiming);
        cudaEventCreateWithFlags(&ev_w1, cudaEventDisableTiming);
        cudaEventCreateWithFlags(&ev_w2, cudaEventDisableTiming);
        cudaFuncSetAttribute(moe_gemm_kernel<DMODEL, DFF, 0>,
                             cudaFuncAttributeMaxDynamicSharedMemorySize, SMEM_TOTAL);
        cudaFuncSetAttribute(moe_gemm_kernel<DFF, DMODEL, 1>,
                             cudaFuncAttributeMaxDynamicSharedMemorySize, SMEM_TOTAL);
    }

    dim3 tb(32, 8);

    // fork both weight transposes immediately
    cudaEventRecord(ev_fork, 0);
    cudaStreamWaitEvent(s2, ev_fork, 0);
    transp_conv_kernel<0><<<dim3(DFF / 32, DMODEL / 64, NEXP), tb, 0, s2>>>(W1);
    cudaEventRecord(ev_w1, s2);
    transp_conv_kernel<1><<<dim3(DMODEL / 32, DFF / 64, NEXP), tb, 0, s2>>>(W2);
    cudaEventRecord(ev_w2, s2);

    // main stream: zero out, gating (fused x convert)
    zero_cnt_kernel<<<1, 32>>>();
    zero_out_kernel<<<(T_TOK * DMODEL) / 4 / 256, 256>>>(out);
    gate_kernel<<<T_TOK / 8, 256>>>(x, Wg);

    cudaStreamWaitEvent(0, ev_w1, 0);
    moe_gemm_kernel<DMODEL, DFF, 0>
        <<<dim3(DFF / BN, T_TOK / BM, NEXP), 256, SMEM_TOTAL>>>(b1, out);

    cudaStreamWaitEvent(0, ev_w2, 0);
    moe_gemm_kernel<DFF, DMODEL, 1>
        <<<dim3(DMODEL / BN, T_TOK / BM, NEXP), 256, SMEM_TOTAL>>>(b2, out);
}